// round 6
// baseline (speedup 1.0000x reference)
#include <cuda_runtime.h>
#include <cuda_fp16.h>
#include <cstdint>

#define V_CONST 163842
#define CIN 64
#define COUT 64
#define TILE_M 128
#define NTHREADS 256
#define NTILES ((V_CONST + TILE_M - 1) / TILE_M)   // 1281
#define MAX_B 2

// ---- persistent device scratch ----
__device__ uint4 gx4[(size_t)MAX_B * V_CONST * CIN / 8];   // x as fp16, row-linear (128B rows)
__device__ uint4 gwf[7 * 2 * 4 * 64];                      // W as B-fragments: (j,ng,k) x lane*2 uint4

// ---- shared memory: 3 x-buffers (16KB each), 128B-pitch rows, 16B XOR swizzle ----
#define BUF_BYTES 16384
#define NBUF 3
#define OFF_BIAS (NBUF * BUF_BYTES)            // 49152
#define SMEM_TOTAL (OFF_BIAS + 256 + 64)

// ---------------- helpers ----------------
__device__ __forceinline__ uint32_t smem_u32(const void* p) {
    uint32_t a;
    asm("{ .reg .u64 t; cvta.to.shared.u64 t, %1; cvt.u32.u64 %0, t; }" : "=r"(a) : "l"(p));
    return a;
}
__device__ __forceinline__ void cpasync16(uint32_t dst, const void* src) {
    asm volatile("cp.async.cg.shared.global [%0], [%1], 16;" :: "r"(dst), "l"(src) : "memory");
}
__device__ __forceinline__ void ldmx4(uint32_t* a, uint32_t addr) {
    asm volatile("ldmatrix.sync.aligned.m8n8.x4.shared.b16 {%0,%1,%2,%3}, [%4];"
                 : "=r"(a[0]), "=r"(a[1]), "=r"(a[2]), "=r"(a[3]) : "r"(addr));
}
__device__ __forceinline__ void mma16816(float* d, const uint32_t* a, const uint32_t* b) {
    asm volatile(
        "mma.sync.aligned.m16n8k16.row.col.f32.f16.f16.f32 "
        "{%0,%1,%2,%3}, {%4,%5,%6,%7}, {%8,%9}, {%0,%1,%2,%3};"
        : "+f"(d[0]), "+f"(d[1]), "+f"(d[2]), "+f"(d[3])
        : "r"(a[0]), "r"(a[1]), "r"(a[2]), "r"(a[3]), "r"(b[0]), "r"(b[1]));
}
__device__ __forceinline__ uint32_t packh2(float a, float b) {
    __half2 h = __floats2half2_rn(a, b);
    return *reinterpret_cast<uint32_t*>(&h);
}

// ---------------- pre-pass A: x fp32 -> fp16 (row-linear) ----------------
__global__ void prep_x(const float* __restrict__ x, size_t total8) {
    size_t i = (size_t)blockIdx.x * blockDim.x + threadIdx.x;
    if (i >= total8) return;
    const float4* s = (const float4*)(x + i * 8);
    float4 a = s[0], b = s[1];
    uint4 o;
    o.x = packh2(a.x, a.y); o.y = packh2(a.z, a.w);
    o.z = packh2(b.x, b.y); o.w = packh2(b.z, b.w);
    gx4[i] = o;
}

// ---------------- pre-pass B: W fp32 -> B-fragments in lane order ----------------
// One block per j. Loads W_j into swizzled smem (exact main-kernel layout), then
// each warp (w -> ng=w&1, k=w>>1) runs the SAME ldmatrix sequence the main loop
// used to run, and dumps the resulting registers to gwf in lane order.
__global__ void prep_w(const float* __restrict__ Wg) {
    __shared__ __align__(16) char ws[8192];
    const int j = blockIdx.x;
    const int tid = threadIdx.x;
    const int lane = tid & 31;
    const int wid = tid >> 5;
    const uint32_t wsb = smem_u32(ws);

    // fill smem: 64 rows x 128B, swizzled
    #pragma unroll
    for (int t = 0; t < 2; t++) {
        const int c = tid * 2 + t;          // 0..511 chunks of 16B
        const int o = c >> 3;
        const int u = c & 7;
        const float* s = Wg + (size_t)o * (7 * CIN) + j * CIN + u * 8;
        uint4 v;
        v.x = packh2(s[0], s[1]); v.y = packh2(s[2], s[3]);
        v.z = packh2(s[4], s[5]); v.w = packh2(s[6], s[7]);
        *(uint4*)(ws + o * 128 + ((u ^ (o & 7)) << 4)) = v;
    }
    __syncthreads();

    const int ng = wid & 1;
    const int k  = wid >> 1;
    const int blane = lane & 7;
    const int bsel = (lane >> 3) & 1;
    const int bnt  = (lane >> 4);

    uint32_t bfr[8];
    #pragma unroll
    for (int np = 0; np < 2; np++) {
        const int br = ng * 32 + np * 16 + bnt * 8 + blane;
        const uint32_t uc = (uint32_t)(2 * k + bsel);
        ldmx4(bfr + 4 * np, wsb + (uint32_t)br * 128 + ((uc ^ (br & 7)) << 4));
    }
    uint4* dst = gwf + (((size_t)j * 2 + ng) * 4 + k) * 64 + lane * 2;
    dst[0] = make_uint4(bfr[0], bfr[1], bfr[2], bfr[3]);
    dst[1] = make_uint4(bfr[4], bfr[5], bfr[6], bfr[7]);
}

// ---------------- main kernel ----------------
__global__ __launch_bounds__(NTHREADS, 4)
void conv_layer_kernel(const void* __restrict__ neigh,
                       const float* __restrict__ bias,
                       float* __restrict__ out)
{
    extern __shared__ char smem[];
    const uint32_t sb = smem_u32(smem);
    const int tid  = threadIdx.x;
    const int wid  = tid >> 5;
    const int lane = tid & 31;
    const int batch = blockIdx.y;
    const long long v0 = (long long)blockIdx.x * TILE_M;

    // detect int64 vs int32 neigh_orders
    uint32_t hiacc = 0;
    {
        const uint2* p = (const uint2*)neigh;
        #pragma unroll
        for (int i = 0; i < 8; i++) hiacc |= p[i].y;
    }
    const bool is64 = (hiacc == 0);

    if (tid < COUT) ((float*)(smem + OFF_BIAS))[tid] = bias[tid];

    // gather mapping: two threads per row, 4 x 16B cp.async each
    const int r = tid >> 1;
    const int h = tid & 1;
    long long vv = v0 + r;
    if (vv >= V_CONST) vv = V_CONST - 1;
    const size_t nb = (size_t)vv * 7;
    const char* gxb = (const char*)gx4 + (size_t)batch * V_CONST * 128;

    auto issue = [&](int jj, int buf) {
        long long u = is64 ? ((const long long*)neigh)[nb + jj]
                           : (long long)((const int*)neigh)[nb + jj];
        if (u < 0) u = 0;
        if (u >= V_CONST) u = V_CONST - 1;
        const char* src = gxb + (size_t)u * 128 + h * 64;
        const uint32_t xB = sb + buf * BUF_BYTES + (uint32_t)r * 128;
        const int rs = r & 7;
        #pragma unroll
        for (int q = 0; q < 4; q++) {
            const uint32_t uc = (uint32_t)(h * 4 + q);
            cpasync16(xB + ((uc ^ rs) << 4), src + q * 16);
        }
        asm volatile("cp.async.commit_group;" ::: "memory");
    };

    float acc[2][4][4];
    #pragma unroll
    for (int mt = 0; mt < 2; mt++)
        #pragma unroll
        for (int n = 0; n < 4; n++)
            #pragma unroll
            for (int q = 0; q < 4; q++) acc[mt][n][q] = 0.0f;

    // warp tiling: 4 M-groups (Mw=32) x 2 N-groups (Nw=32)
    const int mg = wid & 3;
    const int ng = wid >> 2;
    const int acol = (lane >> 4);
    const uint4* wf0 = gwf + ((size_t)ng * 4) * 64 + lane * 2;   // + j*8*64 + k*64

    issue(0, 0);

    for (int j = 0; j < 7; j++) {
        const int buf = j % NBUF;
        if (j < 6) issue(j + 1, (j + 1) % NBUF);

        if (j < 6) asm volatile("cp.async.wait_group 1;" ::: "memory");
        else       asm volatile("cp.async.wait_group 0;" ::: "memory");
        __syncthreads();   // single barrier per j (NBUF=3 covers WAR on reuse)

        const uint32_t xhB = sb + buf * BUF_BYTES;
        const uint4* wfj = wf0 + (size_t)j * 8 * 64;

        #pragma unroll
        for (int k = 0; k < 4; k++) {
            // B frags: 2 x LDG.128 from fragment-ordered W (L1-resident)
            uint4 b0 = wfj[(size_t)k * 64 + 0];
            uint4 b1 = wfj[(size_t)k * 64 + 1];
            uint32_t bfr[4][2] = {
                {b0.x, b0.y}, {b0.z, b0.w}, {b1.x, b1.y}, {b1.z, b1.w}
            };
            // A frags: 2 x ldmatrix.x4 (two 16-row m-tiles)
            uint32_t afr[2][4];
            #pragma unroll
            for (int mt = 0; mt < 2; mt++) {
                const int ar = mg * 32 + mt * 16 + (lane & 15);
                const uint32_t uc = (uint32_t)(2 * k + acol);
                ldmx4(afr[mt], xhB + (uint32_t)ar * 128 + ((uc ^ (ar & 7)) << 4));
            }
            #pragma unroll
            for (int mt = 0; mt < 2; mt++)
                #pragma unroll
                for (int n = 0; n < 4; n++)
                    mma16816(acc[mt][n], afr[mt], bfr[n]);
        }
    }

    // ---------------- epilogue ----------------
    {
        const float* bs = (const float*)(smem + OFF_BIAS);
        const size_t obase = (size_t)batch * V_CONST * COUT;
        #pragma unroll
        for (int mt = 0; mt < 2; mt++) {
            const long long row0 = v0 + mg * 32 + mt * 16 + (lane >> 2);
            #pragma unroll
            for (int n = 0; n < 4; n++) {
                const int c = ng * 32 + n * 8 + (lane & 3) * 2;
                const float b0 = bs[c], b1 = bs[c + 1];
                if (row0 < V_CONST) {
                    float2 v; v.x = acc[mt][n][0] + b0; v.y = acc[mt][n][1] + b1;
                    *(float2*)(out + obase + (size_t)row0 * COUT + c) = v;
                }
                if (row0 + 8 < V_CONST) {
                    float2 v; v.x = acc[mt][n][2] + b0; v.y = acc[mt][n][3] + b1;
                    *(float2*)(out + obase + (size_t)(row0 + 8) * COUT + c) = v;
                }
            }
        }
    }
}

// ---------------- launch ----------------
extern "C" void kernel_launch(void* const* d_in, const int* in_sizes, int n_in,
                              void* d_out, int out_size) {
    const float* x     = (const float*)d_in[0];
    const void*  neigh = d_in[1];
    const float* Wg    = (const float*)d_in[2];
    const float* b     = (const float*)d_in[3];
    float* out = (float*)d_out;

    const int B = in_sizes[0] / (V_CONST * CIN);   // = 2

    const size_t total8 = (size_t)B * V_CONST * CIN / 8;
    prep_x<<<(unsigned)((total8 + 255) / 256), 256>>>(x, total8);
    prep_w<<<7, 256>>>(Wg);

    cudaFuncSetAttribute(conv_layer_kernel,
                         cudaFuncAttributeMaxDynamicSharedMemorySize, SMEM_TOTAL);
    dim3 grid(NTILES, B);
    conv_layer_kernel<<<grid, NTHREADS, SMEM_TOTAL>>>(neigh, b, out);
}

// round 7
// speedup vs baseline: 1.4915x; 1.4915x over previous
#include <cuda_runtime.h>
#include <cuda_fp16.h>
#include <cstdint>

#define V_CONST 163842
#define CIN 64
#define COUT 64
#define TILE_M 128
#define NTHREADS 256
#define NTILES ((V_CONST + TILE_M - 1) / TILE_M)   // 1281
#define MAX_B 2

// ---- persistent device scratch ----
__device__ uint4 gx4[(size_t)MAX_B * V_CONST * CIN / 8];   // x as fp16, row-linear (128B rows)
__device__ uint4 gwf[7 * 2 * 4 * 64];                      // W as B-fragments: (j,ng,k) x lane*2 uint4

// ---- shared memory: 3 x-buffers (16KB each), 128B-pitch rows, 16B XOR swizzle ----
#define BUF_BYTES 16384
#define NBUF 3
#define OFF_BIAS (NBUF * BUF_BYTES)            // 49152
#define SMEM_TOTAL (OFF_BIAS + 256 + 64)

// ---------------- helpers ----------------
__device__ __forceinline__ uint32_t smem_u32(const void* p) {
    uint32_t a;
    asm("{ .reg .u64 t; cvta.to.shared.u64 t, %1; cvt.u32.u64 %0, t; }" : "=r"(a) : "l"(p));
    return a;
}
__device__ __forceinline__ void cpasync16(uint32_t dst, const void* src) {
    asm volatile("cp.async.cg.shared.global [%0], [%1], 16;" :: "r"(dst), "l"(src) : "memory");
}
__device__ __forceinline__ void ldmx4(uint32_t* a, uint32_t addr) {
    asm volatile("ldmatrix.sync.aligned.m8n8.x4.shared.b16 {%0,%1,%2,%3}, [%4];"
                 : "=r"(a[0]), "=r"(a[1]), "=r"(a[2]), "=r"(a[3]) : "r"(addr));
}
__device__ __forceinline__ void mma16816(float* d, const uint32_t* a, const uint32_t* b) {
    asm volatile(
        "mma.sync.aligned.m16n8k16.row.col.f32.f16.f16.f32 "
        "{%0,%1,%2,%3}, {%4,%5,%6,%7}, {%8,%9}, {%0,%1,%2,%3};"
        : "+f"(d[0]), "+f"(d[1]), "+f"(d[2]), "+f"(d[3])
        : "r"(a[0]), "r"(a[1]), "r"(a[2]), "r"(a[3]), "r"(b[0]), "r"(b[1]));
}
__device__ __forceinline__ uint32_t packh2(float a, float b) {
    __half2 h = __floats2half2_rn(a, b);
    return *reinterpret_cast<uint32_t*>(&h);
}

// ---------------- pre-pass A: x fp32 -> fp16 (row-linear) ----------------
__global__ void prep_x(const float* __restrict__ x, size_t total8) {
    size_t i = (size_t)blockIdx.x * blockDim.x + threadIdx.x;
    if (i >= total8) return;
    const float4* s = (const float4*)(x + i * 8);
    float4 a = s[0], b = s[1];
    uint4 o;
    o.x = packh2(a.x, a.y); o.y = packh2(a.z, a.w);
    o.z = packh2(b.x, b.y); o.w = packh2(b.z, b.w);
    gx4[i] = o;
}

// ---------------- pre-pass B: W fp32 -> B-fragments in lane order ----------------
__global__ void prep_w(const float* __restrict__ Wg) {
    __shared__ __align__(16) char ws[8192];
    const int j = blockIdx.x;
    const int tid = threadIdx.x;
    const int lane = tid & 31;
    const int wid = tid >> 5;
    const uint32_t wsb = smem_u32(ws);

    // fill smem: 64 rows x 128B, swizzled (exact main-kernel layout)
    #pragma unroll
    for (int t = 0; t < 2; t++) {
        const int c = tid * 2 + t;          // 0..511 chunks of 16B
        const int o = c >> 3;
        const int u = c & 7;
        const float* s = Wg + (size_t)o * (7 * CIN) + j * CIN + u * 8;
        uint4 v;
        v.x = packh2(s[0], s[1]); v.y = packh2(s[2], s[3]);
        v.z = packh2(s[4], s[5]); v.w = packh2(s[6], s[7]);
        *(uint4*)(ws + o * 128 + ((u ^ (o & 7)) << 4)) = v;
    }
    __syncthreads();

    const int ng = wid & 1;
    const int k  = wid >> 1;
    const int blane = lane & 7;
    const int bsel = (lane >> 3) & 1;
    const int bnt  = (lane >> 4);

    uint32_t bfr[8];
    #pragma unroll
    for (int np = 0; np < 2; np++) {
        const int br = ng * 32 + np * 16 + bnt * 8 + blane;
        const uint32_t uc = (uint32_t)(2 * k + bsel);
        ldmx4(bfr + 4 * np, wsb + (uint32_t)br * 128 + ((uc ^ (br & 7)) << 4));
    }
    uint4* dst = gwf + (((size_t)j * 2 + ng) * 4 + k) * 64 + lane * 2;
    dst[0] = make_uint4(bfr[0], bfr[1], bfr[2], bfr[3]);
    dst[1] = make_uint4(bfr[4], bfr[5], bfr[6], bfr[7]);
}

// ---------------- main kernel ----------------
__global__ __launch_bounds__(NTHREADS, 3)   // 85-reg cap: NO spills (R6 lesson)
void conv_layer_kernel(const void* __restrict__ neigh,
                       const float* __restrict__ bias,
                       float* __restrict__ out)
{
    extern __shared__ char smem[];
    const uint32_t sb = smem_u32(smem);
    const int tid  = threadIdx.x;
    const int wid  = tid >> 5;
    const int lane = tid & 31;
    const int batch = blockIdx.y;
    const long long v0 = (long long)blockIdx.x * TILE_M;

    // detect int64 vs int32 neigh_orders
    uint32_t hiacc = 0;
    {
        const uint2* p = (const uint2*)neigh;
        #pragma unroll
        for (int i = 0; i < 8; i++) hiacc |= p[i].y;
    }
    const bool is64 = (hiacc == 0);

    if (tid < COUT) ((float*)(smem + OFF_BIAS))[tid] = bias[tid];

    // gather mapping: two threads per row, 4 x 16B cp.async each
    const int r = tid >> 1;
    const int h = tid & 1;
    long long vv = v0 + r;
    if (vv >= V_CONST) vv = V_CONST - 1;

    // preload all 7 neighbor indices (clamped) — off the critical path
    unsigned uidx[7];
    {
        const size_t nb = (size_t)vv * 7;
        #pragma unroll
        for (int j = 0; j < 7; j++) {
            long long u = is64 ? ((const long long*)neigh)[nb + j]
                               : (long long)((const int*)neigh)[nb + j];
            if (u < 0) u = 0;
            if (u >= V_CONST) u = V_CONST - 1;
            uidx[j] = (unsigned)u;
        }
    }
    const char* gxb = (const char*)gx4 + (size_t)batch * V_CONST * 128;

    auto issue = [&](int jj, int buf) {
        const char* src = gxb + (size_t)uidx[jj] * 128 + h * 64;
        const uint32_t xB = sb + buf * BUF_BYTES + (uint32_t)r * 128;
        const int rs = r & 7;
        #pragma unroll
        for (int q = 0; q < 4; q++) {
            const uint32_t uc = (uint32_t)(h * 4 + q);
            cpasync16(xB + ((uc ^ rs) << 4), src + q * 16);
        }
        asm volatile("cp.async.commit_group;" ::: "memory");
    };

    float acc[2][4][4];
    #pragma unroll
    for (int mt = 0; mt < 2; mt++)
        #pragma unroll
        for (int n = 0; n < 4; n++)
            #pragma unroll
            for (int q = 0; q < 4; q++) acc[mt][n][q] = 0.0f;

    // warp tiling: 4 M-groups (Mw=32) x 2 N-groups (Nw=32)
    const int mg = wid & 3;
    const int ng = wid >> 2;
    const int acol = (lane >> 4);
    const uint4* wf0 = gwf + ((size_t)ng * 4) * 64 + lane * 2;   // + j*8*64 + k*64

    issue(0, 0);

    for (int j = 0; j < 7; j++) {
        const int buf = j % NBUF;
        if (j < 6) issue(j + 1, (j + 1) % NBUF);

        if (j < 6) asm volatile("cp.async.wait_group 1;" ::: "memory");
        else       asm volatile("cp.async.wait_group 0;" ::: "memory");
        __syncthreads();   // single barrier per j (NBUF=3 covers WAR on reuse)

        const uint32_t xhB = sb + buf * BUF_BYTES;
        const uint4* wfj = wf0 + (size_t)j * 8 * 64;

        #pragma unroll
        for (int k = 0; k < 4; k++) {
            // B frags: 2 x LDG.128 from fragment-ordered W (L1/L2-resident)
            uint4 b0 = wfj[(size_t)k * 64 + 0];
            uint4 b1 = wfj[(size_t)k * 64 + 1];
            uint32_t bfr[4][2] = {
                {b0.x, b0.y}, {b0.z, b0.w}, {b1.x, b1.y}, {b1.z, b1.w}
            };
            // A frags: 2 x ldmatrix.x4 (two 16-row m-tiles)
            uint32_t afr[2][4];
            #pragma unroll
            for (int mt = 0; mt < 2; mt++) {
                const int ar = mg * 32 + mt * 16 + (lane & 15);
                const uint32_t uc = (uint32_t)(2 * k + acol);
                ldmx4(afr[mt], xhB + (uint32_t)ar * 128 + ((uc ^ (ar & 7)) << 4));
            }
            #pragma unroll
            for (int mt = 0; mt < 2; mt++)
                #pragma unroll
                for (int n = 0; n < 4; n++)
                    mma16816(acc[mt][n], afr[mt], bfr[n]);
        }
    }

    // ---------------- epilogue ----------------
    {
        const float* bs = (const float*)(smem + OFF_BIAS);
        const size_t obase = (size_t)batch * V_CONST * COUT;
        #pragma unroll
        for (int mt = 0; mt < 2; mt++) {
            const long long row0 = v0 + mg * 32 + mt * 16 + (lane >> 2);
            #pragma unroll
            for (int n = 0; n < 4; n++) {
                const int c = ng * 32 + n * 8 + (lane & 3) * 2;
                const float b0 = bs[c], b1 = bs[c + 1];
                if (row0 < V_CONST) {
                    float2 v; v.x = acc[mt][n][0] + b0; v.y = acc[mt][n][1] + b1;
                    *(float2*)(out + obase + (size_t)row0 * COUT + c) = v;
                }
                if (row0 + 8 < V_CONST) {
                    float2 v; v.x = acc[mt][n][2] + b0; v.y = acc[mt][n][3] + b1;
                    *(float2*)(out + obase + (size_t)(row0 + 8) * COUT + c) = v;
                }
            }
        }
    }
}

// ---------------- launch ----------------
extern "C" void kernel_launch(void* const* d_in, const int* in_sizes, int n_in,
                              void* d_out, int out_size) {
    const float* x     = (const float*)d_in[0];
    const void*  neigh = d_in[1];
    const float* Wg    = (const float*)d_in[2];
    const float* b     = (const float*)d_in[3];
    float* out = (float*)d_out;

    const int B = in_sizes[0] / (V_CONST * CIN);   // = 2

    const size_t total8 = (size_t)B * V_CONST * CIN / 8;
    prep_x<<<(unsigned)((total8 + 255) / 256), 256>>>(x, total8);
    prep_w<<<7, 256>>>(Wg);

    cudaFuncSetAttribute(conv_layer_kernel,
                         cudaFuncAttributeMaxDynamicSharedMemorySize, SMEM_TOTAL);
    dim3 grid(NTILES, B);
    conv_layer_kernel<<<grid, NTHREADS, SMEM_TOTAL>>>(neigh, b, out);
}

// round 8
// speedup vs baseline: 1.5395x; 1.0322x over previous
#include <cuda_runtime.h>
#include <cuda_fp16.h>
#include <cstdint>

#define V_CONST 163842
#define CIN 64
#define COUT 64
#define TILE_M 128
#define NTHREADS 256
#define NTILES ((V_CONST + TILE_M - 1) / TILE_M)   // 1281
#define MAX_B 2

// ---- persistent device scratch ----
__device__ uint4 gx4[(size_t)MAX_B * V_CONST * CIN / 8];   // x as fp16, row-linear (128B rows)
__device__ uint4 gw4[7 * 64 * 64 / 8];                     // W as fp16, pre-swizzled per j (8KB blocks)

// ---- shared memory: 2 buffers (x 16KB + W 8KB each) + idx stage ----
#define WOFF 16384
#define BUF_BYTES 24576
#define NBUF 2
#define OFF_IDX (NBUF * BUF_BYTES)                 // 49152
#define SMEM_TOTAL (OFF_IDX + TILE_M * 7 * 4 + 32) // ~52.8KB -> 4 CTAs/SM

// ---------------- helpers ----------------
__device__ __forceinline__ uint32_t smem_u32(const void* p) {
    uint32_t a;
    asm("{ .reg .u64 t; cvta.to.shared.u64 t, %1; cvt.u32.u64 %0, t; }" : "=r"(a) : "l"(p));
    return a;
}
__device__ __forceinline__ void cpasync16(uint32_t dst, const void* src) {
    asm volatile("cp.async.cg.shared.global [%0], [%1], 16;" :: "r"(dst), "l"(src) : "memory");
}
__device__ __forceinline__ void ldmx4(uint32_t* a, uint32_t addr) {
    asm volatile("ldmatrix.sync.aligned.m8n8.x4.shared.b16 {%0,%1,%2,%3}, [%4];"
                 : "=r"(a[0]), "=r"(a[1]), "=r"(a[2]), "=r"(a[3]) : "r"(addr));
}
__device__ __forceinline__ void mma16816(float* d, const uint32_t* a, const uint32_t* b) {
    asm volatile(
        "mma.sync.aligned.m16n8k16.row.col.f32.f16.f16.f32 "
        "{%0,%1,%2,%3}, {%4,%5,%6,%7}, {%8,%9}, {%0,%1,%2,%3};"
        : "+f"(d[0]), "+f"(d[1]), "+f"(d[2]), "+f"(d[3])
        : "r"(a[0]), "r"(a[1]), "r"(a[2]), "r"(a[3]), "r"(b[0]), "r"(b[1]));
}
__device__ __forceinline__ uint32_t packh2(float a, float b) {
    __half2 h = __floats2half2_rn(a, b);
    return *reinterpret_cast<uint32_t*>(&h);
}

// ---------------- pre-pass (fused): x fp32->fp16 row-linear; W fp32->fp16 pre-swizzled ----------------
__global__ void prep_kernel(const float* __restrict__ x, const float* __restrict__ Wg,
                            size_t total8, unsigned xblocks) {
    if (blockIdx.x < xblocks) {
        size_t i = (size_t)blockIdx.x * blockDim.x + threadIdx.x;
        if (i >= total8) return;
        const float4* s = (const float4*)(x + i * 8);
        float4 a = s[0], b = s[1];
        uint4 o;
        o.x = packh2(a.x, a.y); o.y = packh2(a.z, a.w);
        o.z = packh2(b.x, b.y); o.w = packh2(b.z, b.w);
        gx4[i] = o;
    } else {
        const int j = blockIdx.x - xblocks;    // 0..6
        const int tid = threadIdx.x;
        #pragma unroll
        for (int t = 0; t < 2; t++) {
            const int c = tid * 2 + t;         // 0..511 16B chunks
            const int o = c >> 3;
            const int u = c & 7;
            const float* s = Wg + (size_t)o * (7 * CIN) + j * CIN + u * 8;
            uint4 v;
            v.x = packh2(s[0], s[1]); v.y = packh2(s[2], s[3]);
            v.z = packh2(s[4], s[5]); v.w = packh2(s[6], s[7]);
            const uint32_t dst = (uint32_t)j * 8192 + (uint32_t)o * 128 + (uint32_t)((u ^ (o & 7)) << 4);
            *(uint4*)((char*)gw4 + dst) = v;
        }
    }
}

// ---------------- main kernel: 4 CTAs/SM, 64-reg cap ----------------
__global__ __launch_bounds__(NTHREADS, 4)
void conv_layer_kernel(const void* __restrict__ neigh,
                       const float* __restrict__ bias,
                       float* __restrict__ out)
{
    extern __shared__ char smem[];
    const uint32_t sb = smem_u32(smem);
    const int tid  = threadIdx.x;
    const int wid  = tid >> 5;
    const int lane = tid & 31;
    const int batch = blockIdx.y;
    const int v0 = blockIdx.x * TILE_M;

    // detect int64 vs int32 neigh_orders
    uint32_t hiacc = 0;
    {
        const uint2* p = (const uint2*)neigh;
        #pragma unroll
        for (int i = 0; i < 8; i++) hiacc |= p[i].y;
    }
    const bool is64 = (hiacc == 0);

    // ---- stage this tile's 7 indices per row into smem (clamped) ----
    const int r = tid >> 1;          // row 0..127 (two threads per row)
    const int h = tid & 1;           // 16B-quad half selector
    unsigned* sidx = (unsigned*)(smem + OFF_IDX);
    if (h == 0) {
        int vv = v0 + r; if (vv >= V_CONST) vv = V_CONST - 1;
        const size_t nb = (size_t)vv * 7;
        #pragma unroll
        for (int j = 0; j < 7; j++) {
            long long u = is64 ? ((const long long*)neigh)[nb + j]
                               : (long long)((const int*)neigh)[nb + j];
            unsigned uu = (unsigned)u;
            if (uu > (unsigned)(V_CONST - 1)) uu = V_CONST - 1;  // also catches negatives
            sidx[r * 7 + j] = uu;
        }
    }
    __syncthreads();

    const char* gxb = (const char*)gx4 + (size_t)batch * V_CONST * 128;

    auto issue = [&](int jj, int buf) {
        const unsigned u = sidx[r * 7 + jj];
        const char* src = gxb + (size_t)u * 128 + h * 64;
        const uint32_t xB = sb + buf * BUF_BYTES + (uint32_t)r * 128;
        const int rs = r & 7;
        #pragma unroll
        for (int q = 0; q < 4; q++) {
            const uint32_t uc = (uint32_t)(h * 4 + q);
            cpasync16(xB + ((uc ^ rs) << 4), src + q * 16);
        }
        // W block jj: 8KB pre-swizzled, linear copy (2 x 16B per thread)
        const char* wsrc = (const char*)gw4 + (size_t)jj * 8192 + (size_t)tid * 32;
        const uint32_t wdst = sb + buf * BUF_BYTES + WOFF + (uint32_t)tid * 32;
        cpasync16(wdst, wsrc);
        cpasync16(wdst + 16, wsrc + 16);
        asm volatile("cp.async.commit_group;" ::: "memory");
    };

    float acc[2][4][4];
    #pragma unroll
    for (int mt = 0; mt < 2; mt++)
        #pragma unroll
        for (int n = 0; n < 4; n++)
            #pragma unroll
            for (int q = 0; q < 4; q++) acc[mt][n][q] = 0.0f;

    // warp tiling: 4 M-groups (Mw=32) x 2 N-groups (Nw=32)
    const int mg = wid & 3;
    const int ng = wid >> 2;
    const int acol = (lane >> 4);
    const int l7 = lane & 7;

    issue(0, 0);

    for (int j = 0; j < 7; j++) {
        const int buf = j & 1;
        if (j < 6) issue(j + 1, buf ^ 1);   // buf^1 freed by trailing sync of j-1

        if (j < 6) asm volatile("cp.async.wait_group 1;" ::: "memory");
        else       asm volatile("cp.async.wait_group 0;" ::: "memory");
        __syncthreads();                     // publish buf to all warps

        const uint32_t xhB = sb + buf * BUF_BYTES;
        const uint32_t whB = xhB + WOFF;

        #pragma unroll
        for (int k = 0; k < 4; k++) {
            // B frags: 2 x ldmatrix.x4 (each covers two n-tiles)
            uint32_t bfr[4][2];
            #pragma unroll
            for (int np = 0; np < 2; np++) {
                const int br = ng * 32 + np * 16 + ((lane >> 4) << 3) + l7;
                const uint32_t uc = (uint32_t)(2 * k + ((lane >> 3) & 1));
                uint32_t t4[4];
                ldmx4(t4, whB + (uint32_t)br * 128 + ((uc ^ (br & 7)) << 4));
                bfr[2 * np + 0][0] = t4[0]; bfr[2 * np + 0][1] = t4[1];
                bfr[2 * np + 1][0] = t4[2]; bfr[2 * np + 1][1] = t4[3];
            }
            // A frags: 2 x ldmatrix.x4 (two 16-row m-tiles)
            uint32_t afr[2][4];
            #pragma unroll
            for (int mt = 0; mt < 2; mt++) {
                const int ar = mg * 32 + mt * 16 + (lane & 15);
                const uint32_t uc = (uint32_t)(2 * k + acol);
                ldmx4(afr[mt], xhB + (uint32_t)ar * 128 + ((uc ^ (ar & 7)) << 4));
            }
            #pragma unroll
            for (int mt = 0; mt < 2; mt++)
                #pragma unroll
                for (int n = 0; n < 4; n++)
                    mma16816(acc[mt][n], afr[mt], bfr[n]);
        }

        if (j < 6) __syncthreads();          // WAR: buf safe to refill at j+1
    }

    // ---------------- epilogue (bias via read-only cache) ----------------
    {
        const size_t obase = (size_t)batch * V_CONST * COUT;
        #pragma unroll
        for (int mt = 0; mt < 2; mt++) {
            const int row0 = v0 + mg * 32 + mt * 16 + (lane >> 2);
            #pragma unroll
            for (int n = 0; n < 4; n++) {
                const int c = ng * 32 + n * 8 + (lane & 3) * 2;
                const float b0 = __ldg(bias + c), b1 = __ldg(bias + c + 1);
                if (row0 < V_CONST) {
                    float2 v; v.x = acc[mt][n][0] + b0; v.y = acc[mt][n][1] + b1;
                    *(float2*)(out + obase + (size_t)row0 * COUT + c) = v;
                }
                if (row0 + 8 < V_CONST) {
                    float2 v; v.x = acc[mt][n][2] + b0; v.y = acc[mt][n][3] + b1;
                    *(float2*)(out + obase + (size_t)(row0 + 8) * COUT + c) = v;
                }
            }
        }
    }
}

// ---------------- launch ----------------
extern "C" void kernel_launch(void* const* d_in, const int* in_sizes, int n_in,
                              void* d_out, int out_size) {
    const float* x     = (const float*)d_in[0];
    const void*  neigh = d_in[1];
    const float* Wg    = (const float*)d_in[2];
    const float* b     = (const float*)d_in[3];
    float* out = (float*)d_out;

    const int B = in_sizes[0] / (V_CONST * CIN);   // = 2

    const size_t total8 = (size_t)B * V_CONST * CIN / 8;
    const unsigned xblocks = (unsigned)((total8 + 255) / 256);
    prep_kernel<<<xblocks + 7, 256>>>(x, Wg, total8, xblocks);

    cudaFuncSetAttribute(conv_layer_kernel,
                         cudaFuncAttributeMaxDynamicSharedMemorySize, SMEM_TOTAL);
    dim3 grid(NTILES, B);
    conv_layer_kernel<<<grid, NTHREADS, SMEM_TOTAL>>>(neigh, b, out);
}